// round 2
// baseline (speedup 1.0000x reference)
#include <cuda_runtime.h>
#include <math.h>

// Problem constants
#define T_SEQ 4096
#define HID   1024
#define G4    4096   // 4*HID
#define KDIM  1024   // E == H

#define REC_NC 128   // recurrent CTAs (1 per SM, all co-resident)

// ---------------- device scratch (static, no allocations) ----------------
__device__ float g_pre[2][T_SEQ][G4];                 // input projections (128 MB)
__device__ float g_hseq[2][T_SEQ][HID];               // per-layer hidden sequence
__device__ __align__(16) float2 g_hbuf[2][HID];       // double-buffered (hA,hB) pairs
__device__ volatile unsigned g_flag[REC_NC];          // per-CTA publish epoch

// ---------------- flag reset (between launches / replays) ----------------
__global__ void reset_flags() { g_flag[threadIdx.x] = 0u; }

// ---------------- SGEMM: pre[b][t][r] = sum_k A_b[t][k]*W[r][k] + (bi[r]+bh[r]) ----
#define BM 128
#define BN 128
#define BK 8

__global__ void __launch_bounds__(256, 2)
sgemm_nt_bias(const float* __restrict__ A0, const float* __restrict__ A1,
              int from_hseq,
              const float* __restrict__ W,
              const float* __restrict__ bi, const float* __restrict__ bh)
{
    __shared__ float As[BK][BM];
    __shared__ float Bs[BK][BN];

    const int z = blockIdx.z;   // branch
    const float* A = from_hseq ? &g_hseq[z][0][0] : (z ? A1 : A0);
    float* C = &g_pre[z][0][0];

    const int m0 = blockIdx.y * BM;
    const int n0 = blockIdx.x * BN;
    const int tid = threadIdx.x;

    const int lr = tid >> 1;          // 0..127 row within tile
    const int lc = (tid & 1) * 4;     // 0 or 4 within k-tile

    float acc[8][8];
    #pragma unroll
    for (int i = 0; i < 8; ++i)
        #pragma unroll
        for (int j = 0; j < 8; ++j) acc[i][j] = 0.f;

    const int tx = tid & 15, ty = tid >> 4;

    for (int k0 = 0; k0 < KDIM; k0 += BK) {
        float4 av = *(const float4*)&A[(size_t)(m0 + lr) * KDIM + k0 + lc];
        float4 bv = *(const float4*)&W[(size_t)(n0 + lr) * KDIM + k0 + lc];
        __syncthreads();
        As[lc + 0][lr] = av.x; As[lc + 1][lr] = av.y;
        As[lc + 2][lr] = av.z; As[lc + 3][lr] = av.w;
        Bs[lc + 0][lr] = bv.x; Bs[lc + 1][lr] = bv.y;
        Bs[lc + 2][lr] = bv.z; Bs[lc + 3][lr] = bv.w;
        __syncthreads();
        #pragma unroll
        for (int kk = 0; kk < BK; ++kk) {
            float4 a0 = *(const float4*)&As[kk][ty * 8];
            float4 a1 = *(const float4*)&As[kk][ty * 8 + 4];
            float4 b0 = *(const float4*)&Bs[kk][tx * 8];
            float4 b1 = *(const float4*)&Bs[kk][tx * 8 + 4];
            float a[8] = {a0.x,a0.y,a0.z,a0.w,a1.x,a1.y,a1.z,a1.w};
            float b[8] = {b0.x,b0.y,b0.z,b0.w,b1.x,b1.y,b1.z,b1.w};
            #pragma unroll
            for (int i = 0; i < 8; ++i)
                #pragma unroll
                for (int j = 0; j < 8; ++j)
                    acc[i][j] = fmaf(a[i], b[j], acc[i][j]);
        }
    }

    float bsum[8];
    #pragma unroll
    for (int j = 0; j < 8; ++j) {
        int n = n0 + tx * 8 + j;
        bsum[j] = bi[n] + bh[n];
    }
    #pragma unroll
    for (int i = 0; i < 8; ++i) {
        int m = m0 + ty * 8 + i;
        float* crow = C + (size_t)m * G4 + n0 + tx * 8;
        float4 v0, v1;
        v0.x = acc[i][0] + bsum[0]; v0.y = acc[i][1] + bsum[1];
        v0.z = acc[i][2] + bsum[2]; v0.w = acc[i][3] + bsum[3];
        v1.x = acc[i][4] + bsum[4]; v1.y = acc[i][5] + bsum[5];
        v1.z = acc[i][6] + bsum[6]; v1.w = acc[i][7] + bsum[7];
        *(float4*)&crow[0] = v0;
        *(float4*)&crow[4] = v1;
    }
}

// ---------------- recurrent kernel: one layer, both branches ----------------
// 128 CTAs x 512 threads (16 warps). CTA c owns 8 hidden units (32 gate rows).
// W stored transposed+vectorized in SMEM: sWv[kk][row] (kk = k/4, row padded 33)
// so a warp's lanes index ROWS (conflict-free) and h is a per-warp BROADCAST.
// Warp w covers k-slice [w*64, w*64+64). Cross-warp reduce via padded SMEM,
// gates gathered with shfl in warp 0. Inter-CTA sync: per-CTA epoch flags.

#define SWV_PAD 33
#define REC_SMEM ((256 * SWV_PAD * 16) + (HID * 8) + (16 * SWV_PAD * 8))

__device__ __forceinline__ float sigm(float x) { return 1.f / (1.f + expf(-x)); }

__global__ void __launch_bounds__(512, 1)
lstm_rec(const float* __restrict__ Whh,     // [4096][1024] this layer
         const float* __restrict__ h0b0, const float* __restrict__ h0b1,
         const float* __restrict__ c0b0, const float* __restrict__ c0b1)
{
    extern __shared__ float smem[];
    float4* sWv  = (float4*)smem;                                   // 256*33 float4
    float2* hs2  = (float2*)(smem + 256 * SWV_PAD * 4);             // 1024 float2
    float2* sred = (float2*)(smem + 256 * SWV_PAD * 4 + 2 * HID);   // 16*33 float2

    const int tid  = threadIdx.x;
    const int warp = tid >> 5;
    const int lane = tid & 31;
    const int cta  = blockIdx.x;
    const int u0   = cta * 8;

    // ---- load W_hh rows into transposed SMEM layout ----
    // rows r = q*8+u map to global gate row gr = q*1024 + u0 + u
    #pragma unroll 1
    for (int i = 0; i < 16; ++i) {
        int idx = i * 512 + tid;
        int r  = idx >> 8;      // 0..31
        int kk = idx & 255;     // 0..255
        int gr = (r >> 3) * HID + u0 + (r & 7);
        float4 v = *(const float4*)&Whh[(size_t)gr * HID + kk * 4];
        sWv[kk * SWV_PAD + r] = v;
    }

    // ---- init cell state + publish h_0 (version 1) ----
    float cA = 0.f, cB = 0.f;
    if (warp == 0) {
        if (lane < 8) {
            cA = c0b0[u0 + lane];
            cB = c0b1[u0 + lane];
            float hA = h0b0[u0 + lane];
            float hB = h0b1[u0 + lane];
            g_hbuf[0][u0 + lane] = make_float2(hA, hB);
        }
        __syncwarp();
        if (lane == 0) {
            __threadfence();
            g_flag[cta] = 1u;
        }
    }

    const float4* wv = sWv + warp * 16 * SWV_PAD + lane;   // kk stride = SWV_PAD
    const float4* h4base = (const float4*)hs2 + warp * 32; // k base = warp*64
    const int gr_lane = (lane >> 3) * HID + u0 + (lane & 7);

    for (int t = 0; t < T_SEQ; ++t) {
        const int p = t & 1;

        float preA = 0.f, preB = 0.f;
        if (warp == 0) {
            // prefetch input-projection gates for this step (independent of h)
            preA = __ldg(&g_pre[0][t][gr_lane]);
            preB = __ldg(&g_pre[1][t][gr_lane]);
            // spin until every CTA has published version t+1
            const unsigned need = (unsigned)(t + 1);
            for (;;) {
                unsigned f0 = g_flag[lane];
                unsigned f1 = g_flag[lane + 32];
                unsigned f2 = g_flag[lane + 64];
                unsigned f3 = g_flag[lane + 96];
                bool ok = (f0 >= need) & (f1 >= need) & (f2 >= need) & (f3 >= need);
                if (__all_sync(0xffffffffu, ok)) break;
            }
            __threadfence();   // acquire: flush L1 so h loads below are fresh
        }
        __syncthreads();       // (a) release all warps

        // stage h (both branches, paired) into SMEM: 8KB = 512 x float4
        ((float4*)hs2)[tid] = ((const float4*)g_hbuf[p])[tid];
        __syncthreads();       // (b)

        // ---- matvec: lane = row, warp = k-slice, h broadcast ----
        float accA = 0.f, accB = 0.f;
        #pragma unroll
        for (int kk = 0; kk < 16; ++kk) {
            float4 w  = wv[kk * SWV_PAD];
            float4 h0v = h4base[kk * 2];       // (A0,B0,A1,B1)
            float4 h1v = h4base[kk * 2 + 1];   // (A2,B2,A3,B3)
            accA = fmaf(w.x, h0v.x, accA); accB = fmaf(w.x, h0v.y, accB);
            accA = fmaf(w.y, h0v.z, accA); accB = fmaf(w.y, h0v.w, accB);
            accA = fmaf(w.z, h1v.x, accA); accB = fmaf(w.z, h1v.y, accB);
            accA = fmaf(w.w, h1v.z, accA); accB = fmaf(w.w, h1v.w, accB);
        }
        sred[warp * SWV_PAD + lane] = make_float2(accA, accB);
        __syncthreads();       // (c)

        if (warp == 0) {
            // reduce 16 warp partials for this row
            float sA = preA, sB = preB;
            #pragma unroll
            for (int w = 0; w < 16; ++w) {
                float2 v = sred[w * SWV_PAD + lane];
                sA += v.x; sB += v.y;
            }
            // gather gates: unit u needs rows u, 8+u, 16+u, 24+u
            const int u = lane & 7;
            float iA = __shfl_sync(0xffffffffu, sA, u);
            float iB = __shfl_sync(0xffffffffu, sB, u);
            float fA = __shfl_sync(0xffffffffu, sA, u + 8);
            float fB = __shfl_sync(0xffffffffu, sB, u + 8);
            float gA = __shfl_sync(0xffffffffu, sA, u + 16);
            float gB = __shfl_sync(0xffffffffu, sB, u + 16);
            float oA = __shfl_sync(0xffffffffu, sA, u + 24);
            float oB = __shfl_sync(0xffffffffu, sB, u + 24);
            if (lane < 8) {
                cA = sigm(fA) * cA + sigm(iA) * tanhf(gA);
                cB = sigm(fB) * cB + sigm(iB) * tanhf(gB);
                float hA = sigm(oA) * tanhf(cA);
                float hB = sigm(oB) * tanhf(cB);
                g_hbuf[p ^ 1][u0 + u] = make_float2(hA, hB);
                g_hseq[0][t][u0 + u] = hA;
                g_hseq[1][t][u0 + u] = hB;
            }
            __syncwarp();
            if (lane == 0) {
                __threadfence();
                g_flag[cta] = (unsigned)(t + 2);   // publish version t+2
            }
        }
        // other warps run ahead to the next iteration's bar (a)
    }
}

// ---------------- final reduction: out = 5*exp(-sum|o1-o2|) ----------------
__global__ void final_k(float* __restrict__ out)
{
    __shared__ float red[256];
    int tid = threadIdx.x;
    float s = 0.f;
    for (int j = tid; j < HID; j += 256) {
        float a = g_hseq[0][T_SEQ - 1][j];
        float b = g_hseq[1][T_SEQ - 1][j];
        s += fabsf(a - b);
    }
    red[tid] = s;
    __syncthreads();
    for (int w = 128; w > 0; w >>= 1) {
        if (tid < w) red[tid] += red[tid + w];
        __syncthreads();
    }
    if (tid == 0) out[0] = 5.f * expf(-red[0]);
}

// ---------------- launch ----------------
extern "C" void kernel_launch(void* const* d_in, const int* in_sizes, int n_in,
                              void* d_out, int out_size)
{
    const float* s1   = (const float*)d_in[0];
    const float* s2   = (const float*)d_in[1];
    const float* h1_0 = (const float*)d_in[2];
    const float* c1_0 = (const float*)d_in[3];
    const float* h2_0 = (const float*)d_in[4];
    const float* c2_0 = (const float*)d_in[5];
    const float* W_ih = (const float*)d_in[6];  // [2][4096][1024]
    const float* W_hh = (const float*)d_in[7];  // [2][4096][1024]
    const float* b_ih = (const float*)d_in[8];  // [2][4096]
    const float* b_hh = (const float*)d_in[9];  // [2][4096]

    cudaFuncSetAttribute(lstm_rec, cudaFuncAttributeMaxDynamicSharedMemorySize, REC_SMEM);

    dim3 gg(G4 / BN, T_SEQ / BM, 2);

    // layer 0
    sgemm_nt_bias<<<gg, 256>>>(s1, s2, 0, W_ih, b_ih, b_hh);
    reset_flags<<<1, REC_NC>>>();
    lstm_rec<<<REC_NC, 512, REC_SMEM>>>(W_hh, h1_0, h2_0, c1_0, c2_0);

    // layer 1 (input = layer-0 hidden sequence)
    const size_t woff = (size_t)G4 * KDIM;
    sgemm_nt_bias<<<gg, 256>>>(nullptr, nullptr, 1, W_ih + woff, b_ih + G4, b_hh + G4);
    reset_flags<<<1, REC_NC>>>();
    lstm_rec<<<REC_NC, 512, REC_SMEM>>>(W_hh + woff, h1_0 + HID, h2_0 + HID,
                                        c1_0 + HID, c2_0 + HID);

    final_k<<<1, 256>>>((float*)d_out);
}

// round 3
// speedup vs baseline: 2.3480x; 2.3480x over previous
#include <cuda_runtime.h>
#include <math.h>

// Problem constants
#define T_SEQ 4096
#define HID   1024
#define G4    4096   // 4*HID
#define KDIM  1024   // E == H

#define REC_NC 128   // recurrent CTAs (1 per SM, all co-resident)

// ---------------- device scratch (static, no allocations) ----------------
__device__ float g_pre[2][T_SEQ][G4];                 // input projections (128 MB)
__device__ float g_hseq[2][T_SEQ][HID];               // per-layer hidden sequence
// LL-style publish buffer: per unit a 16B packet {hA, tag, hB, tag}, double-buffered
__device__ __align__(16) float4 g_hpub[2][HID];

// ---------------- tag reset (before each recurrent launch / replay) ------
__global__ void reset_pub() {
    float4 z = make_float4(0.f, 0.f, 0.f, 0.f);
    int i = threadIdx.x;                  // 512 threads
    ((float4*)g_hpub)[i]        = z;
    ((float4*)g_hpub)[i + 512]  = z;
    ((float4*)g_hpub)[i + 1024] = z;
    ((float4*)g_hpub)[i + 1536] = z;
}

// ---------------- SGEMM: pre[b][t][r] = sum_k A_b[t][k]*W[r][k] + bias ----
#define BM 128
#define BN 128
#define BK 8

__global__ void __launch_bounds__(256, 2)
sgemm_nt_bias(const float* __restrict__ A0, const float* __restrict__ A1,
              int from_hseq,
              const float* __restrict__ W,
              const float* __restrict__ bi, const float* __restrict__ bh)
{
    __shared__ float As[BK][BM];
    __shared__ float Bs[BK][BN];

    const int z = blockIdx.z;   // branch
    const float* A = from_hseq ? &g_hseq[z][0][0] : (z ? A1 : A0);
    float* C = &g_pre[z][0][0];

    const int m0 = blockIdx.y * BM;
    const int n0 = blockIdx.x * BN;
    const int tid = threadIdx.x;

    const int lr = tid >> 1;          // 0..127 row within tile
    const int lc = (tid & 1) * 4;     // 0 or 4 within k-tile

    float acc[8][8];
    #pragma unroll
    for (int i = 0; i < 8; ++i)
        #pragma unroll
        for (int j = 0; j < 8; ++j) acc[i][j] = 0.f;

    const int tx = tid & 15, ty = tid >> 4;

    // prefetch first k-tile
    float4 av = *(const float4*)&A[(size_t)(m0 + lr) * KDIM + lc];
    float4 bv = *(const float4*)&W[(size_t)(n0 + lr) * KDIM + lc];

    for (int k0 = 0; k0 < KDIM; k0 += BK) {
        __syncthreads();
        As[lc + 0][lr] = av.x; As[lc + 1][lr] = av.y;
        As[lc + 2][lr] = av.z; As[lc + 3][lr] = av.w;
        Bs[lc + 0][lr] = bv.x; Bs[lc + 1][lr] = bv.y;
        Bs[lc + 2][lr] = bv.z; Bs[lc + 3][lr] = bv.w;
        __syncthreads();
        if (k0 + BK < KDIM) {   // prefetch next tile during compute
            av = *(const float4*)&A[(size_t)(m0 + lr) * KDIM + k0 + BK + lc];
            bv = *(const float4*)&W[(size_t)(n0 + lr) * KDIM + k0 + BK + lc];
        }
        #pragma unroll
        for (int kk = 0; kk < BK; ++kk) {
            float4 a0 = *(const float4*)&As[kk][ty * 8];
            float4 a1 = *(const float4*)&As[kk][ty * 8 + 4];
            float4 b0 = *(const float4*)&Bs[kk][tx * 8];
            float4 b1 = *(const float4*)&Bs[kk][tx * 8 + 4];
            float a[8] = {a0.x,a0.y,a0.z,a0.w,a1.x,a1.y,a1.z,a1.w};
            float b[8] = {b0.x,b0.y,b0.z,b0.w,b1.x,b1.y,b1.z,b1.w};
            #pragma unroll
            for (int i = 0; i < 8; ++i)
                #pragma unroll
                for (int j = 0; j < 8; ++j)
                    acc[i][j] = fmaf(a[i], b[j], acc[i][j]);
        }
    }

    float bsum[8];
    #pragma unroll
    for (int j = 0; j < 8; ++j) {
        int n = n0 + tx * 8 + j;
        bsum[j] = bi[n] + bh[n];
    }
    #pragma unroll
    for (int i = 0; i < 8; ++i) {
        int m = m0 + ty * 8 + i;
        float* crow = C + (size_t)m * G4 + n0 + tx * 8;
        float4 v0, v1;
        v0.x = acc[i][0] + bsum[0]; v0.y = acc[i][1] + bsum[1];
        v0.z = acc[i][2] + bsum[2]; v0.w = acc[i][3] + bsum[3];
        v1.x = acc[i][4] + bsum[4]; v1.y = acc[i][5] + bsum[5];
        v1.z = acc[i][6] + bsum[6]; v1.w = acc[i][7] + bsum[7];
        *(float4*)&crow[0] = v0;
        *(float4*)&crow[4] = v1;
    }
}

// ---------------- recurrent kernel: one layer, both branches ----------------
// 128 CTAs x 512 threads (16 warps). CTA c owns 8 hidden units (32 gate rows),
// W transposed+vectorized in SMEM (sWv[kk][row], pad 33): lanes index rows
// (conflict-free), h is a warp broadcast. Warp w covers k-slice [w*64,w*64+64).
// Inter-CTA sync: NCCL-LL-style tagged packets, no fences, no flags.

#define SWV_PAD 33
#define REC_SMEM ((256 * SWV_PAD * 16) + (HID * 8) + (16 * SWV_PAD * 8))

__device__ __forceinline__ float sigm(float x) { return 1.f / (1.f + expf(-x)); }

__device__ __forceinline__ void publish16(float4* p, float hA, float hB, unsigned tag) {
    float tf = __uint_as_float(tag);
    asm volatile("st.volatile.global.v4.f32 [%0], {%1,%2,%3,%4};"
                 :: "l"(p), "f"(hA), "f"(tf), "f"(hB), "f"(tf) : "memory");
}

__global__ void __launch_bounds__(512, 1)
lstm_rec(const float* __restrict__ Whh,     // [4096][1024] this layer
         const float* __restrict__ h0b0, const float* __restrict__ h0b1,
         const float* __restrict__ c0b0, const float* __restrict__ c0b1)
{
    extern __shared__ float smem[];
    float4* sWv  = (float4*)smem;                                   // 256*33 float4
    float2* hs2  = (float2*)(smem + 256 * SWV_PAD * 4);             // 1024 float2
    float2* sred = (float2*)(smem + 256 * SWV_PAD * 4 + 2 * HID);   // 16*33 float2

    const int tid  = threadIdx.x;
    const int warp = tid >> 5;
    const int lane = tid & 31;
    const int cta  = blockIdx.x;
    const int u0   = cta * 8;

    // ---- load W_hh rows into transposed SMEM layout ----
    #pragma unroll 1
    for (int i = 0; i < 16; ++i) {
        int idx = i * 512 + tid;
        int r  = idx >> 8;      // 0..31
        int kk = idx & 255;     // 0..255
        int gr = (r >> 3) * HID + u0 + (r & 7);
        float4 v = *(const float4*)&Whh[(size_t)gr * HID + kk * 4];
        sWv[kk * SWV_PAD + r] = v;
    }

    // ---- init cell state + publish h^(0) with tag 1 into buffer 0 ----
    float cA = 0.f, cB = 0.f;
    if (warp == 0 && lane < 8) {
        cA = c0b0[u0 + lane];
        cB = c0b1[u0 + lane];
        float hA = h0b0[u0 + lane];
        float hB = h0b1[u0 + lane];
        publish16(&g_hpub[0][u0 + lane], hA, hB, 1u);
    }

    const float4* wv = sWv + warp * 16 * SWV_PAD + lane;   // kk stride = SWV_PAD
    const float4* h4base = (const float4*)hs2 + warp * 32; // k base = warp*64
    const int gr_lane = (lane >> 3) * HID + u0 + (lane & 7);
    const int uA = tid;            // units this thread polls/stages
    const int uB = tid + 512;

    for (int t = 0; t < T_SEQ; ++t) {
        const int p = t & 1;
        const unsigned tag = (unsigned)(t + 1);

        float preA = 0.f, preB = 0.f;
        if (warp == 0) {
            preA = __ldg(&g_pre[0][t][gr_lane]);
            preB = __ldg(&g_pre[1][t][gr_lane]);
        }

        // ---- poll + stage h^(t): each thread owns 2 units ----
        {
            const float4* pub = g_hpub[p];
            float4 v0, v1;
            bool ok0 = false, ok1 = false;
            do {
                if (!ok0) {
                    v0 = __ldcv(&pub[uA]);
                    ok0 = (__float_as_uint(v0.y) == tag) & (__float_as_uint(v0.w) == tag);
                }
                if (!ok1) {
                    v1 = __ldcv(&pub[uB]);
                    ok1 = (__float_as_uint(v1.y) == tag) & (__float_as_uint(v1.w) == tag);
                }
            } while (!(ok0 && ok1));
            hs2[uA] = make_float2(v0.x, v0.z);
            hs2[uB] = make_float2(v1.x, v1.z);
        }
        __syncthreads();   // hs2 complete

        // ---- matvec: lane = row, warp = k-slice, h broadcast ----
        float accA = 0.f, accB = 0.f;
        #pragma unroll
        for (int kk = 0; kk < 16; ++kk) {
            float4 w   = wv[kk * SWV_PAD];
            float4 h0v = h4base[kk * 2];       // (A0,B0,A1,B1)
            float4 h1v = h4base[kk * 2 + 1];   // (A2,B2,A3,B3)
            accA = fmaf(w.x, h0v.x, accA); accB = fmaf(w.x, h0v.y, accB);
            accA = fmaf(w.y, h0v.z, accA); accB = fmaf(w.y, h0v.w, accB);
            accA = fmaf(w.z, h1v.x, accA); accB = fmaf(w.z, h1v.y, accB);
            accA = fmaf(w.w, h1v.z, accA); accB = fmaf(w.w, h1v.w, accB);
        }
        sred[warp * SWV_PAD + lane] = make_float2(accA, accB);
        __syncthreads();   // sred complete; non-warp0 warps run ahead to next poll

        if (warp == 0) {
            float sA = preA, sB = preB;
            #pragma unroll
            for (int w = 0; w < 16; ++w) {
                float2 v = sred[w * SWV_PAD + lane];
                sA += v.x; sB += v.y;
            }
            // gather gates: unit u needs rows u, 8+u, 16+u, 24+u
            const int u = lane & 7;
            float iA = __shfl_sync(0xffffffffu, sA, u);
            float iB = __shfl_sync(0xffffffffu, sB, u);
            float fA = __shfl_sync(0xffffffffu, sA, u + 8);
            float fB = __shfl_sync(0xffffffffu, sB, u + 8);
            float gA = __shfl_sync(0xffffffffu, sA, u + 16);
            float gB = __shfl_sync(0xffffffffu, sB, u + 16);
            float oA = __shfl_sync(0xffffffffu, sA, u + 24);
            float oB = __shfl_sync(0xffffffffu, sB, u + 24);
            if (lane < 8) {
                cA = sigm(fA) * cA + sigm(iA) * tanhf(gA);
                cB = sigm(fB) * cB + sigm(iB) * tanhf(gB);
                float hA = sigm(oA) * tanhf(cA);
                float hB = sigm(oB) * tanhf(cB);
                // publish h^(t+1) into buffer (t+1)&1 with tag t+2
                publish16(&g_hpub[p ^ 1][u0 + u], hA, hB, (unsigned)(t + 2));
                g_hseq[0][t][u0 + u] = hA;
                g_hseq[1][t][u0 + u] = hB;
            }
        }
    }
}

// ---------------- final reduction: out = 5*exp(-sum|o1-o2|) ----------------
__global__ void final_k(float* __restrict__ out)
{
    __shared__ float red[256];
    int tid = threadIdx.x;
    float s = 0.f;
    for (int j = tid; j < HID; j += 256) {
        float a = g_hseq[0][T_SEQ - 1][j];
        float b = g_hseq[1][T_SEQ - 1][j];
        s += fabsf(a - b);
    }
    red[tid] = s;
    __syncthreads();
    for (int w = 128; w > 0; w >>= 1) {
        if (tid < w) red[tid] += red[tid + w];
        __syncthreads();
    }
    if (tid == 0) out[0] = 5.f * expf(-red[0]);
}

// ---------------- launch ----------------
extern "C" void kernel_launch(void* const* d_in, const int* in_sizes, int n_in,
                              void* d_out, int out_size)
{
    const float* s1   = (const float*)d_in[0];
    const float* s2   = (const float*)d_in[1];
    const float* h1_0 = (const float*)d_in[2];
    const float* c1_0 = (const float*)d_in[3];
    const float* h2_0 = (const float*)d_in[4];
    const float* c2_0 = (const float*)d_in[5];
    const float* W_ih = (const float*)d_in[6];  // [2][4096][1024]
    const float* W_hh = (const float*)d_in[7];  // [2][4096][1024]
    const float* b_ih = (const float*)d_in[8];  // [2][4096]
    const float* b_hh = (const float*)d_in[9];  // [2][4096]

    cudaFuncSetAttribute(lstm_rec, cudaFuncAttributeMaxDynamicSharedMemorySize, REC_SMEM);

    dim3 gg(G4 / BN, T_SEQ / BM, 2);

    // layer 0
    sgemm_nt_bias<<<gg, 256>>>(s1, s2, 0, W_ih, b_ih, b_hh);
    reset_pub<<<1, 512>>>();
    lstm_rec<<<REC_NC, 512, REC_SMEM>>>(W_hh, h1_0, h2_0, c1_0, c2_0);

    // layer 1 (input = layer-0 hidden sequence)
    const size_t woff = (size_t)G4 * KDIM;
    sgemm_nt_bias<<<gg, 256>>>(nullptr, nullptr, 1, W_ih + woff, b_ih + G4, b_hh + G4);
    reset_pub<<<1, 512>>>();
    lstm_rec<<<REC_NC, 512, REC_SMEM>>>(W_hh + woff, h1_0 + HID, h2_0 + HID,
                                        c1_0 + HID, c2_0 + HID);

    final_k<<<1, 256>>>((float*)d_out);
}

// round 4
// speedup vs baseline: 2.7826x; 1.1851x over previous
#include <cuda_runtime.h>
#include <math.h>

// Problem constants
#define T_SEQ 4096
#define HID   1024
#define G4    4096   // 4*HID
#define KDIM  1024   // E == H

#define REC_NC 128   // recurrent CTAs (1 per SM, all co-resident)

// ---------------- device scratch (static, no allocations) ----------------
__device__ float g_pre[2][T_SEQ][G4];                 // input projections (128 MB)
__device__ float g_hseq[2][T_SEQ][HID];               // per-layer hidden sequence
// LL-style publish buffer: per unit a 16B packet {hA, tag, hB, tag}, double-buffered
__device__ __align__(16) float4 g_hpub[2][HID];

// ---------------- tag reset (before each recurrent launch / replay) ------
__global__ void reset_pub() {
    float4 z = make_float4(0.f, 0.f, 0.f, 0.f);
    int i = threadIdx.x;                  // 512 threads
    ((float4*)g_hpub)[i]        = z;
    ((float4*)g_hpub)[i + 512]  = z;
    ((float4*)g_hpub)[i + 1024] = z;
    ((float4*)g_hpub)[i + 1536] = z;
}

// ---------------- SGEMM: pre[b][t][r] = sum_k A_b[t][k]*W[r][k] + bias ----
// Ping-pong SMEM double buffering: one __syncthreads per k-tile.
#define BM 128
#define BN 128
#define BK 8

__global__ void __launch_bounds__(256, 2)
sgemm_nt_bias(const float* __restrict__ A0, const float* __restrict__ A1,
              int from_hseq,
              const float* __restrict__ W,
              const float* __restrict__ bi, const float* __restrict__ bh)
{
    __shared__ float As[2][BK][BM];
    __shared__ float Bs[2][BK][BN];

    const int z = blockIdx.z;   // branch
    const float* A = from_hseq ? &g_hseq[z][0][0] : (z ? A1 : A0);
    float* C = &g_pre[z][0][0];

    const int m0 = blockIdx.y * BM;
    const int n0 = blockIdx.x * BN;
    const int tid = threadIdx.x;

    const int lr = tid >> 1;          // 0..127 row within tile
    const int lc = (tid & 1) * 4;     // 0 or 4 within k-tile

    float acc[8][8];
    #pragma unroll
    for (int i = 0; i < 8; ++i)
        #pragma unroll
        for (int j = 0; j < 8; ++j) acc[i][j] = 0.f;

    const int tx = tid & 15, ty = tid >> 4;

    // stage 0
    {
        float4 av = *(const float4*)&A[(size_t)(m0 + lr) * KDIM + lc];
        float4 bv = *(const float4*)&W[(size_t)(n0 + lr) * KDIM + lc];
        As[0][lc + 0][lr] = av.x; As[0][lc + 1][lr] = av.y;
        As[0][lc + 2][lr] = av.z; As[0][lc + 3][lr] = av.w;
        Bs[0][lc + 0][lr] = bv.x; Bs[0][lc + 1][lr] = bv.y;
        Bs[0][lc + 2][lr] = bv.z; Bs[0][lc + 3][lr] = bv.w;
    }
    __syncthreads();

    int p = 0;
    for (int k0 = 0; k0 < KDIM; k0 += BK) {
        if (k0 + BK < KDIM) {   // load next tile into the other buffer
            float4 av = *(const float4*)&A[(size_t)(m0 + lr) * KDIM + k0 + BK + lc];
            float4 bv = *(const float4*)&W[(size_t)(n0 + lr) * KDIM + k0 + BK + lc];
            As[p ^ 1][lc + 0][lr] = av.x; As[p ^ 1][lc + 1][lr] = av.y;
            As[p ^ 1][lc + 2][lr] = av.z; As[p ^ 1][lc + 3][lr] = av.w;
            Bs[p ^ 1][lc + 0][lr] = bv.x; Bs[p ^ 1][lc + 1][lr] = bv.y;
            Bs[p ^ 1][lc + 2][lr] = bv.z; Bs[p ^ 1][lc + 3][lr] = bv.w;
        }
        #pragma unroll
        for (int kk = 0; kk < BK; ++kk) {
            float4 a0 = *(const float4*)&As[p][kk][ty * 8];
            float4 a1 = *(const float4*)&As[p][kk][ty * 8 + 4];
            float4 b0 = *(const float4*)&Bs[p][kk][tx * 8];
            float4 b1 = *(const float4*)&Bs[p][kk][tx * 8 + 4];
            float a[8] = {a0.x,a0.y,a0.z,a0.w,a1.x,a1.y,a1.z,a1.w};
            float b[8] = {b0.x,b0.y,b0.z,b0.w,b1.x,b1.y,b1.z,b1.w};
            #pragma unroll
            for (int i = 0; i < 8; ++i)
                #pragma unroll
                for (int j = 0; j < 8; ++j)
                    acc[i][j] = fmaf(a[i], b[j], acc[i][j]);
        }
        p ^= 1;
        __syncthreads();
    }

    float bsum[8];
    #pragma unroll
    for (int j = 0; j < 8; ++j) {
        int n = n0 + tx * 8 + j;
        bsum[j] = bi[n] + bh[n];
    }
    #pragma unroll
    for (int i = 0; i < 8; ++i) {
        int m = m0 + ty * 8 + i;
        float* crow = C + (size_t)m * G4 + n0 + tx * 8;
        float4 v0, v1;
        v0.x = acc[i][0] + bsum[0]; v0.y = acc[i][1] + bsum[1];
        v0.z = acc[i][2] + bsum[2]; v0.w = acc[i][3] + bsum[3];
        v1.x = acc[i][4] + bsum[4]; v1.y = acc[i][5] + bsum[5];
        v1.z = acc[i][6] + bsum[6]; v1.w = acc[i][7] + bsum[7];
        *(float4*)&crow[0] = v0;
        *(float4*)&crow[4] = v1;
    }
}

// ---------------- recurrent kernel: one layer, both branches ----------------
// 128 CTAs x 512 threads (16 warps). CTA c owns 8 hidden units (32 gate rows).
// Weights live in REGISTERS: thread (warp w, lane l) holds row r=l,
// k-slice [w*64, w*64+64) = 16 float4. h is staged in SMEM and read as
// per-warp broadcasts. Cross-warp reduce via padded SMEM; gate gather via
// shfl in warp 0. Inter-CTA sync: NCCL-LL tagged packets (no fences).

#define SRED_PAD 33
#define REC_SMEM ((HID * 8) + (16 * SRED_PAD * 8))

__device__ __forceinline__ float sigm(float x) {
    return 1.f / (1.f + __expf(-x));
}

__device__ __forceinline__ void publish16(float4* p, float hA, float hB, unsigned tag) {
    float tf = __uint_as_float(tag);
    asm volatile("st.volatile.global.v4.f32 [%0], {%1,%2,%3,%4};"
                 :: "l"(p), "f"(hA), "f"(tf), "f"(hB), "f"(tf) : "memory");
}

__global__ void __launch_bounds__(512, 1)
lstm_rec(const float* __restrict__ Whh,     // [4096][1024] this layer
         const float* __restrict__ h0b0, const float* __restrict__ h0b1,
         const float* __restrict__ c0b0, const float* __restrict__ c0b1)
{
    extern __shared__ float smem[];
    float2* hs2  = (float2*)smem;                 // 1024 float2 (hA,hB)
    float2* sred = (float2*)(smem + 2 * HID);     // 16*33 float2

    const int tid  = threadIdx.x;
    const int warp = tid >> 5;
    const int lane = tid & 31;
    const int cta  = blockIdx.x;
    const int u0   = cta * 8;

    // ---- weights into registers: row = lane, k in [warp*64, warp*64+64) ----
    const int gr_lane = (lane >> 3) * HID + u0 + (lane & 7);  // global gate row
    float4 wreg[16];
    {
        const float4* wrow = (const float4*)&Whh[(size_t)gr_lane * KDIM + warp * 64];
        #pragma unroll
        for (int j = 0; j < 16; ++j) wreg[j] = __ldg(&wrow[j]);
    }

    // ---- init cell state + publish h^(0) with tag 1 into buffer 0 ----
    float cA = 0.f, cB = 0.f;
    if (warp == 0 && lane < 8) {
        cA = c0b0[u0 + lane];
        cB = c0b1[u0 + lane];
        float hA = h0b0[u0 + lane];
        float hB = h0b1[u0 + lane];
        publish16(&g_hpub[0][u0 + lane], hA, hB, 1u);
    }

    const float4* h4base = (const float4*)hs2 + warp * 32; // k base = warp*64
    const int uA = tid;            // units this thread polls/stages
    const int uB = tid + 512;

    for (int t = 0; t < T_SEQ; ++t) {
        const int p = t & 1;
        const unsigned tag = (unsigned)(t + 1);

        float preA = 0.f, preB = 0.f;
        if (warp == 0) {
            preA = __ldg(&g_pre[0][t][gr_lane]);
            preB = __ldg(&g_pre[1][t][gr_lane]);
        }

        // ---- poll + stage h^(t): each thread owns 2 units ----
        {
            const float4* pub = g_hpub[p];
            float4 v0, v1;
            bool ok0 = false, ok1 = false;
            do {
                if (!ok0) {
                    v0 = __ldcv(&pub[uA]);
                    ok0 = (__float_as_uint(v0.y) == tag) & (__float_as_uint(v0.w) == tag);
                }
                if (!ok1) {
                    v1 = __ldcv(&pub[uB]);
                    ok1 = (__float_as_uint(v1.y) == tag) & (__float_as_uint(v1.w) == tag);
                }
            } while (!(ok0 && ok1));
            hs2[uA] = make_float2(v0.x, v0.z);
            hs2[uB] = make_float2(v1.x, v1.z);
        }
        __syncthreads();   // hs2 complete

        // ---- matvec: weights in regs, h broadcast from SMEM ----
        float accA = 0.f, accB = 0.f;
        #pragma unroll
        for (int j = 0; j < 16; ++j) {
            float4 w   = wreg[j];
            float4 h0v = h4base[j * 2];       // (A0,B0,A1,B1)
            float4 h1v = h4base[j * 2 + 1];   // (A2,B2,A3,B3)
            accA = fmaf(w.x, h0v.x, accA); accB = fmaf(w.x, h0v.y, accB);
            accA = fmaf(w.y, h0v.z, accA); accB = fmaf(w.y, h0v.w, accB);
            accA = fmaf(w.z, h1v.x, accA); accB = fmaf(w.z, h1v.y, accB);
            accA = fmaf(w.w, h1v.z, accA); accB = fmaf(w.w, h1v.w, accB);
        }
        sred[warp * SRED_PAD + lane] = make_float2(accA, accB);
        __syncthreads();   // sred complete; non-warp0 warps run ahead to next poll

        if (warp == 0) {
            float sA = preA, sB = preB;
            #pragma unroll
            for (int w = 0; w < 16; ++w) {
                float2 v = sred[w * SRED_PAD + lane];
                sA += v.x; sB += v.y;
            }
            // gather gates: unit u needs rows u, 8+u, 16+u, 24+u
            const int u = lane & 7;
            float iA = __shfl_sync(0xffffffffu, sA, u);
            float iB = __shfl_sync(0xffffffffu, sB, u);
            float fA = __shfl_sync(0xffffffffu, sA, u + 8);
            float fB = __shfl_sync(0xffffffffu, sB, u + 8);
            float gA = __shfl_sync(0xffffffffu, sA, u + 16);
            float gB = __shfl_sync(0xffffffffu, sB, u + 16);
            float oA = __shfl_sync(0xffffffffu, sA, u + 24);
            float oB = __shfl_sync(0xffffffffu, sB, u + 24);
            if (lane < 8) {
                cA = sigm(fA) * cA + sigm(iA) * tanhf(gA);
                cB = sigm(fB) * cB + sigm(iB) * tanhf(gB);
                float hA = sigm(oA) * tanhf(cA);
                float hB = sigm(oB) * tanhf(cB);
                // publish h^(t+1) into buffer (t+1)&1 with tag t+2
                publish16(&g_hpub[p ^ 1][u0 + u], hA, hB, (unsigned)(t + 2));
                g_hseq[0][t][u0 + u] = hA;
                g_hseq[1][t][u0 + u] = hB;
            }
        }
    }
}

// ---------------- final reduction: out = 5*exp(-sum|o1-o2|) ----------------
__global__ void final_k(float* __restrict__ out)
{
    __shared__ float red[256];
    int tid = threadIdx.x;
    float s = 0.f;
    for (int j = tid; j < HID; j += 256) {
        float a = g_hseq[0][T_SEQ - 1][j];
        float b = g_hseq[1][T_SEQ - 1][j];
        s += fabsf(a - b);
    }
    red[tid] = s;
    __syncthreads();
    for (int w = 128; w > 0; w >>= 1) {
        if (tid < w) red[tid] += red[tid + w];
        __syncthreads();
    }
    if (tid == 0) out[0] = 5.f * expf(-red[0]);
}

// ---------------- launch ----------------
extern "C" void kernel_launch(void* const* d_in, const int* in_sizes, int n_in,
                              void* d_out, int out_size)
{
    const float* s1   = (const float*)d_in[0];
    const float* s2   = (const float*)d_in[1];
    const float* h1_0 = (const float*)d_in[2];
    const float* c1_0 = (const float*)d_in[3];
    const float* h2_0 = (const float*)d_in[4];
    const float* c2_0 = (const float*)d_in[5];
    const float* W_ih = (const float*)d_in[6];  // [2][4096][1024]
    const float* W_hh = (const float*)d_in[7];  // [2][4096][1024]
    const float* b_ih = (const float*)d_in[8];  // [2][4096]
    const float* b_hh = (const float*)d_in[9];  // [2][4096]

    cudaFuncSetAttribute(lstm_rec, cudaFuncAttributeMaxDynamicSharedMemorySize, REC_SMEM);

    dim3 gg(G4 / BN, T_SEQ / BM, 2);

    // layer 0
    sgemm_nt_bias<<<gg, 256>>>(s1, s2, 0, W_ih, b_ih, b_hh);
    reset_pub<<<1, 512>>>();
    lstm_rec<<<REC_NC, 512, REC_SMEM>>>(W_hh, h1_0, h2_0, c1_0, c2_0);

    // layer 1 (input = layer-0 hidden sequence)
    const size_t woff = (size_t)G4 * KDIM;
    sgemm_nt_bias<<<gg, 256>>>(nullptr, nullptr, 1, W_ih + woff, b_ih + G4, b_hh + G4);
    reset_pub<<<1, 512>>>();
    lstm_rec<<<REC_NC, 512, REC_SMEM>>>(W_hh + woff, h1_0 + HID, h2_0 + HID,
                                        c1_0 + HID, c2_0 + HID);

    final_k<<<1, 256>>>((float*)d_out);
}

// round 5
// speedup vs baseline: 3.4623x; 1.2442x over previous
#include <cuda_runtime.h>
#include <math.h>

// Problem constants
#define T_SEQ 4096
#define HID   1024
#define G4    4096   // 4*HID
#define KDIM  1024   // E == H

#define REC_NC 128   // recurrent CTAs (1 per SM, all co-resident)

// ---------------- device scratch (static, no allocations) ----------------
__device__ float g_pre[2][T_SEQ][G4];                 // input projections (128 MB)
__device__ float g_hseq[2][T_SEQ][HID];               // per-layer hidden sequence
// LL-style publish buffers: per unit an 8B packet {h, tag}; per branch, double-buffered
__device__ __align__(8) float2 g_pubA[2][HID];
__device__ __align__(8) float2 g_pubB[2][HID];

// ---------------- tag reset (before each recurrent launch / replay) ------
__global__ void reset_pub() {
    float2 z = make_float2(0.f, 0.f);
    int i = threadIdx.x;                  // 512 threads
    #pragma unroll
    for (int j = 0; j < 4; ++j) {
        ((float2*)g_pubA)[i + j * 512] = z;
        ((float2*)g_pubB)[i + j * 512] = z;
    }
}

// ---------------- SGEMM: pre[b][t][r] = sum_k A_b[t][k]*W[r][k] + bias ----
// Ping-pong SMEM double buffering: one __syncthreads per k-tile.
#define BM 128
#define BN 128
#define BK 8

__global__ void __launch_bounds__(256, 2)
sgemm_nt_bias(const float* __restrict__ A0, const float* __restrict__ A1,
              int from_hseq,
              const float* __restrict__ W,
              const float* __restrict__ bi, const float* __restrict__ bh)
{
    __shared__ float As[2][BK][BM];
    __shared__ float Bs[2][BK][BN];

    const int z = blockIdx.z;   // branch
    const float* A = from_hseq ? &g_hseq[z][0][0] : (z ? A1 : A0);
    float* C = &g_pre[z][0][0];

    const int m0 = blockIdx.y * BM;
    const int n0 = blockIdx.x * BN;
    const int tid = threadIdx.x;

    const int lr = tid >> 1;          // 0..127 row within tile
    const int lc = (tid & 1) * 4;     // 0 or 4 within k-tile

    float acc[8][8];
    #pragma unroll
    for (int i = 0; i < 8; ++i)
        #pragma unroll
        for (int j = 0; j < 8; ++j) acc[i][j] = 0.f;

    const int tx = tid & 15, ty = tid >> 4;

    // stage 0
    {
        float4 av = *(const float4*)&A[(size_t)(m0 + lr) * KDIM + lc];
        float4 bv = *(const float4*)&W[(size_t)(n0 + lr) * KDIM + lc];
        As[0][lc + 0][lr] = av.x; As[0][lc + 1][lr] = av.y;
        As[0][lc + 2][lr] = av.z; As[0][lc + 3][lr] = av.w;
        Bs[0][lc + 0][lr] = bv.x; Bs[0][lc + 1][lr] = bv.y;
        Bs[0][lc + 2][lr] = bv.z; Bs[0][lc + 3][lr] = bv.w;
    }
    __syncthreads();

    int p = 0;
    for (int k0 = 0; k0 < KDIM; k0 += BK) {
        if (k0 + BK < KDIM) {   // load next tile into the other buffer
            float4 av = *(const float4*)&A[(size_t)(m0 + lr) * KDIM + k0 + BK + lc];
            float4 bv = *(const float4*)&W[(size_t)(n0 + lr) * KDIM + k0 + BK + lc];
            As[p ^ 1][lc + 0][lr] = av.x; As[p ^ 1][lc + 1][lr] = av.y;
            As[p ^ 1][lc + 2][lr] = av.z; As[p ^ 1][lc + 3][lr] = av.w;
            Bs[p ^ 1][lc + 0][lr] = bv.x; Bs[p ^ 1][lc + 1][lr] = bv.y;
            Bs[p ^ 1][lc + 2][lr] = bv.z; Bs[p ^ 1][lc + 3][lr] = bv.w;
        }
        #pragma unroll
        for (int kk = 0; kk < BK; ++kk) {
            float4 a0 = *(const float4*)&As[p][kk][ty * 8];
            float4 a1 = *(const float4*)&As[p][kk][ty * 8 + 4];
            float4 b0 = *(const float4*)&Bs[p][kk][tx * 8];
            float4 b1 = *(const float4*)&Bs[p][kk][tx * 8 + 4];
            float a[8] = {a0.x,a0.y,a0.z,a0.w,a1.x,a1.y,a1.z,a1.w};
            float b[8] = {b0.x,b0.y,b0.z,b0.w,b1.x,b1.y,b1.z,b1.w};
            #pragma unroll
            for (int i = 0; i < 8; ++i)
                #pragma unroll
                for (int j = 0; j < 8; ++j)
                    acc[i][j] = fmaf(a[i], b[j], acc[i][j]);
        }
        p ^= 1;
        __syncthreads();
    }

    float bsum[8];
    #pragma unroll
    for (int j = 0; j < 8; ++j) {
        int n = n0 + tx * 8 + j;
        bsum[j] = bi[n] + bh[n];
    }
    #pragma unroll
    for (int i = 0; i < 8; ++i) {
        int m = m0 + ty * 8 + i;
        float* crow = C + (size_t)m * G4 + n0 + tx * 8;
        float4 v0, v1;
        v0.x = acc[i][0] + bsum[0]; v0.y = acc[i][1] + bsum[1];
        v0.z = acc[i][2] + bsum[2]; v0.w = acc[i][3] + bsum[3];
        v1.x = acc[i][4] + bsum[4]; v1.y = acc[i][5] + bsum[5];
        v1.z = acc[i][6] + bsum[6]; v1.w = acc[i][7] + bsum[7];
        *(float4*)&crow[0] = v0;
        *(float4*)&crow[4] = v1;
    }
}

// ---------------- recurrent kernel: one layer, both branches ----------------
// 128 CTAs x 512 threads (16 warps). CTA c owns 8 hidden units (32 gate rows).
// Weights in REGISTERS: thread (warp w, lane l) holds row l, k in [64w,64w+64).
// Each warp POLLS ITS OWN k-slice of h packets (8 producer CTAs), stages into
// its private hs2 region, __syncwarp, matvec. One __syncthreads per step, then
// the tail is split: warp0 = branch A, warp1 = branch B (8B LL packets each).

#define SRED_PAD 33
// hs2: 1024 float2 (8KB); sredA[2][16*33] + sredB[2][16*33] floats
#define SRED_BUF (16 * SRED_PAD)
#define REC_SMEM ((HID * 8) + (4 * SRED_BUF * 4))

__device__ __forceinline__ float sigm(float x) {
    return 1.f / (1.f + __expf(-x));
}

__device__ __forceinline__ void publish8(float2* p, float h, unsigned tag) {
    asm volatile("st.volatile.global.v2.f32 [%0], {%1,%2};"
                 :: "l"(p), "f"(h), "f"(__uint_as_float(tag)) : "memory");
}

__device__ __forceinline__ float2 poll8(const float2* p) {
    float2 v;
    asm volatile("ld.volatile.global.v2.f32 {%0,%1}, [%2];"
                 : "=f"(v.x), "=f"(v.y) : "l"(p) : "memory");
    return v;
}

__global__ void __launch_bounds__(512, 1)
lstm_rec(const float* __restrict__ Whh,     // [4096][1024] this layer
         const float* __restrict__ h0b0, const float* __restrict__ h0b1,
         const float* __restrict__ c0b0, const float* __restrict__ c0b1)
{
    extern __shared__ float smem[];
    float2* hs2   = (float2*)smem;                    // 1024 float2 (hA,hB)
    float*  sredA = smem + 2 * HID;                   // [2][16*33]
    float*  sredB = smem + 2 * HID + 2 * SRED_BUF;    // [2][16*33]

    const int tid  = threadIdx.x;
    const int warp = tid >> 5;
    const int lane = tid & 31;
    const int cta  = blockIdx.x;
    const int u0   = cta * 8;

    // ---- weights into registers: row = lane, k in [warp*64, warp*64+64) ----
    const int gr_lane = (lane >> 3) * HID + u0 + (lane & 7);  // global gate row
    float4 wreg[16];
    {
        const float4* wrow = (const float4*)&Whh[(size_t)gr_lane * KDIM + warp * 64];
        #pragma unroll
        for (int j = 0; j < 16; ++j) wreg[j] = __ldg(&wrow[j]);
    }

    // ---- init cell state + publish h^(0) with tag 1 into buffer 0 ----
    float cst = 0.f;   // cA in warp0, cB in warp1 (lanes 0..7)
    if (warp == 0 && lane < 8) {
        cst = c0b0[u0 + lane];
        publish8(&g_pubA[0][u0 + lane], h0b0[u0 + lane], 1u);
    } else if (warp == 1 && lane < 8) {
        cst = c0b1[u0 + lane];
        publish8(&g_pubB[0][u0 + lane], h0b1[u0 + lane], 1u);
    }

    const float4* h4base = (const float4*)hs2 + warp * 32; // k base = warp*64
    const int uP0 = warp * 64 + lane;        // units this thread polls/stages
    const int uP1 = warp * 64 + 32 + lane;

    for (int t = 0; t < T_SEQ; ++t) {
        const int p = t & 1;
        const unsigned tag = (unsigned)(t + 1);

        float pre = 0.f;
        if (warp == 0)      pre = __ldg(&g_pre[0][t][gr_lane]);
        else if (warp == 1) pre = __ldg(&g_pre[1][t][gr_lane]);

        // ---- poll own slice (4 packets/thread), stage into private region ----
        {
            const float2* pA = g_pubA[p];
            const float2* pB = g_pubB[p];
            float2 a0, a1, b0, b1;
            bool o0 = false, o1 = false, o2 = false, o3 = false;
            do {
                if (!o0) { a0 = poll8(&pA[uP0]); o0 = (__float_as_uint(a0.y) == tag); }
                if (!o1) { a1 = poll8(&pA[uP1]); o1 = (__float_as_uint(a1.y) == tag); }
                if (!o2) { b0 = poll8(&pB[uP0]); o2 = (__float_as_uint(b0.y) == tag); }
                if (!o3) { b1 = poll8(&pB[uP1]); o3 = (__float_as_uint(b1.y) == tag); }
            } while (!(o0 & o1 & o2 & o3));
            hs2[uP0] = make_float2(a0.x, b0.x);
            hs2[uP1] = make_float2(a1.x, b1.x);
        }
        __syncwarp();   // own slice staged; no block barrier needed

        // ---- matvec: weights in regs, h broadcast from own SMEM region ----
        float accA = 0.f, accB = 0.f;
        #pragma unroll
        for (int j = 0; j < 16; ++j) {
            float4 w   = wreg[j];
            float4 h0v = h4base[j * 2];       // units 4j,4j+1: (A,B,A,B)
            float4 h1v = h4base[j * 2 + 1];   // units 4j+2,4j+3
            accA = fmaf(w.x, h0v.x, accA); accB = fmaf(w.x, h0v.y, accB);
            accA = fmaf(w.y, h0v.z, accA); accB = fmaf(w.y, h0v.w, accB);
            accA = fmaf(w.z, h1v.x, accA); accB = fmaf(w.z, h1v.y, accB);
            accA = fmaf(w.w, h1v.z, accA); accB = fmaf(w.w, h1v.w, accB);
        }
        sredA[p * SRED_BUF + warp * SRED_PAD + lane] = accA;
        sredB[p * SRED_BUF + warp * SRED_PAD + lane] = accB;
        __syncthreads();   // sred complete; warps 2..15 run ahead to next poll

        if (warp < 2) {
            const float* sr = (warp == 0) ? &sredA[p * SRED_BUF] : &sredB[p * SRED_BUF];
            float s = pre;
            #pragma unroll
            for (int w = 0; w < 16; ++w) s += sr[w * SRED_PAD + lane];
            // gather gates: unit u needs rows u, 8+u, 16+u, 24+u
            const int u = lane & 7;
            float gi = __shfl_sync(0xffffffffu, s, u);
            float gf = __shfl_sync(0xffffffffu, s, u + 8);
            float gg = __shfl_sync(0xffffffffu, s, u + 16);
            float go = __shfl_sync(0xffffffffu, s, u + 24);
            if (lane < 8) {
                cst = sigm(gf) * cst + sigm(gi) * tanhf(gg);
                float hv = sigm(go) * tanhf(cst);
                if (warp == 0) {
                    publish8(&g_pubA[p ^ 1][u0 + u], hv, (unsigned)(t + 2));
                    g_hseq[0][t][u0 + u] = hv;
                } else {
                    publish8(&g_pubB[p ^ 1][u0 + u], hv, (unsigned)(t + 2));
                    g_hseq[1][t][u0 + u] = hv;
                }
            }
        }
    }
}

// ---------------- final reduction: out = 5*exp(-sum|o1-o2|) ----------------
__global__ void final_k(float* __restrict__ out)
{
    __shared__ float red[256];
    int tid = threadIdx.x;
    float s = 0.f;
    for (int j = tid; j < HID; j += 256) {
        float a = g_hseq[0][T_SEQ - 1][j];
        float b = g_hseq[1][T_SEQ - 1][j];
        s += fabsf(a - b);
    }
    red[tid] = s;
    __syncthreads();
    for (int w = 128; w > 0; w >>= 1) {
        if (tid < w) red[tid] += red[tid + w];
        __syncthreads();
    }
    if (tid == 0) out[0] = 5.f * expf(-red[0]);
}

// ---------------- launch ----------------
extern "C" void kernel_launch(void* const* d_in, const int* in_sizes, int n_in,
                              void* d_out, int out_size)
{
    const float* s1   = (const float*)d_in[0];
    const float* s2   = (const float*)d_in[1];
    const float* h1_0 = (const float*)d_in[2];
    const float* c1_0 = (const float*)d_in[3];
    const float* h2_0 = (const float*)d_in[4];
    const float* c2_0 = (const float*)d_in[5];
    const float* W_ih = (const float*)d_in[6];  // [2][4096][1024]
    const float* W_hh = (const float*)d_in[7];  // [2][4096][1024]
    const float* b_ih = (const float*)d_in[8];  // [2][4096]
    const float* b_hh = (const float*)d_in[9];  // [2][4096]

    cudaFuncSetAttribute(lstm_rec, cudaFuncAttributeMaxDynamicSharedMemorySize, REC_SMEM);

    dim3 gg(G4 / BN, T_SEQ / BM, 2);

    // layer 0
    sgemm_nt_bias<<<gg, 256>>>(s1, s2, 0, W_ih, b_ih, b_hh);
    reset_pub<<<1, 512>>>();
    lstm_rec<<<REC_NC, 512, REC_SMEM>>>(W_hh, h1_0, h2_0, c1_0, c2_0);

    // layer 1 (input = layer-0 hidden sequence)
    const size_t woff = (size_t)G4 * KDIM;
    sgemm_nt_bias<<<gg, 256>>>(nullptr, nullptr, 1, W_ih + woff, b_ih + G4, b_hh + G4);
    reset_pub<<<1, 512>>>();
    lstm_rec<<<REC_NC, 512, REC_SMEM>>>(W_hh + woff, h1_0 + HID, h2_0 + HID,
                                        c1_0 + HID, c2_0 + HID);

    final_k<<<1, 256>>>((float*)d_out);
}